// round 1
// baseline (speedup 1.0000x reference)
#include <cuda_runtime.h>
#include <math.h>

#define QN 2048
#define NPTS 32768
#define DM 256
#define KNN 8
#define NH 8
#define HDIM 64
#define STATE 64
#define DINN 512
#define CONVN 640
#define NPROJN 1160
#define HIDN 1024
#define CSZ 64
#define NCH 32

// ---------------- scratch (device globals; no allocation allowed) ----------------
__device__ float g_q[QN*DM];
__device__ float g_feat[QN*KNN*DM];
__device__ float g_v[QN*KNN*DM];
__device__ float g_w[QN*DM];
__device__ float g_x[QN*DM];
__device__ float g_xn[QN*DM];
__device__ float g_tmp[QN*DM];
__device__ int   g_idx[QN*KNN];
__device__ int   g_inv[2*QN];
__device__ float g_xs[2*QN*DM];
__device__ float g_proj[2*QN*NPROJN];
__device__ float g_xbc[2*QN*CONVN];
__device__ float g_dts[2*QN*NH];
__device__ float g_Las[2*QN*NH];
__device__ float g_P[2*NH*NCH*CSZ*CSZ];
__device__ float g_Hc[2*NH*NCH*HDIM*STATE];
__device__ float g_Hin[2*NH*NCH*HDIM*STATE];
__device__ float g_y[2*QN*DINN];
__device__ float g_gated[2*QN*DINN];
__device__ float g_ssmout[2*QN*DM];
__device__ float g_ffnh[QN*HIDN];

__device__ __forceinline__ float sigmoidf_(float x){ return 1.f/(1.f+expf(-x)); }

__device__ __forceinline__ float blockSum256(float v, volatile float* red){
  #pragma unroll
  for (int o=16;o;o>>=1) v += __shfl_down_sync(0xffffffffu, v, o);
  if ((threadIdx.x&31)==0) red[threadIdx.x>>5]=v;
  __syncthreads();
  float s = red[0]+red[1]+red[2]+red[3]+red[4]+red[5]+red[6]+red[7];
  __syncthreads();
  return s;
}

// ---------------- KNN: 1 warp per query, 8 queries/block, smem point tiles ----------------
#define TPTS 2048
__global__ void knn_kernel(const float* __restrict__ qpos, const float* __restrict__ spos){
  __shared__ float sp[TPTS*3];
  int warp = threadIdx.x>>5, lane = threadIdx.x&31;
  int q = blockIdx.x*8 + warp;
  float qx=qpos[q*3+0], qy=qpos[q*3+1], qz=qpos[q*3+2];
  float qq = qx*qx+qy*qy+qz*qz;
  float bd[8]; int bi[8];
  #pragma unroll
  for (int j=0;j<8;j++){ bd[j]=3.0e38f; bi[j]=0x7fffffff; }
  for (int tile=0;tile<NPTS/TPTS;tile++){
    __syncthreads();
    for (int i=threadIdx.x;i<TPTS*3;i+=256) sp[i]=spos[tile*TPTS*3+i];
    __syncthreads();
    for (int p=lane;p<TPTS;p+=32){
      float sx=sp[3*p], sy=sp[3*p+1], sz=sp[3*p+2];
      float ss = sx*sx+sy*sy+sz*sz;
      float dot = qx*sx+qy*sy+qz*sz;
      float d2 = qq + ss - 2.f*dot;   // same formula as reference for tie behavior
      if (d2 < bd[7]){
        bd[7]=d2; bi[7]=tile*TPTS+p;
        for (int j=7;j>0;j--){
          if (bd[j]<bd[j-1]){ float td=bd[j];bd[j]=bd[j-1];bd[j-1]=td;
                              int ti=bi[j];bi[j]=bi[j-1];bi[j-1]=ti; }
          else break;
        }
      }
    }
  }
  // butterfly merge of sorted 8-lists across the warp
  for (int off=16;off;off>>=1){
    float od[8]; int oi[8];
    #pragma unroll
    for (int j=0;j<8;j++){
      od[j]=__shfl_xor_sync(0xffffffffu,bd[j],off);
      oi[j]=__shfl_xor_sync(0xffffffffu,bi[j],off);
    }
    float nd[8]; int ni[8]; int a=0,c=0;
    for (int t=0;t<8;t++){
      bool mine;
      if (a>=8) mine=false;
      else if (c>=8) mine=true;
      else mine = (bd[a]<od[c]) || (bd[a]==od[c] && bi[a]<=oi[c]);
      if (mine){ nd[t]=bd[a];ni[t]=bi[a];a++; } else { nd[t]=od[c];ni[t]=oi[c];c++; }
    }
    for (int j=0;j<8;j++){ bd[j]=nd[j]; bi[j]=ni[j]; }
  }
  if (lane==0){
    #pragma unroll
    for (int j=0;j<8;j++) g_idx[q*8+j]=bi[j];
  }
}

__global__ void gather_feat_kernel(const float* __restrict__ feats){
  int qk=blockIdx.x;
  int src=g_idx[qk];
  g_feat[qk*DM+threadIdx.x]=feats[src*DM+threadIdx.x];
}

__global__ void inv_kernel(const int* __restrict__ order){
  int id=blockIdx.x*blockDim.x+threadIdx.x;
  if (id<2*QN) g_inv[(id/QN)*QN + order[id]] = id%QN;
}

// ---------------- generic fp32 GEMM: C[M,N] = A[M,K] * B[N,K]^T (+bias, optional exact-gelu) ----------------
__global__ void gemm_kernel(const float* __restrict__ A, const float* __restrict__ B,
                            const float* __restrict__ bias, float* __restrict__ Cmat,
                            int M, int Nn, int Kk, int act){
  __shared__ float As[16][17], Bs[16][17];
  int tx=threadIdx.x, ty=threadIdx.y;
  int row=blockIdx.y*16+ty, col=blockIdx.x*16+tx;
  float acc=0.f;
  for (int k0=0;k0<Kk;k0+=16){
    int ka=k0+tx;
    As[ty][tx] = (row<M && ka<Kk)? A[row*Kk+ka] : 0.f;
    int rb=blockIdx.x*16+ty;
    Bs[ty][tx] = (rb<Nn && ka<Kk)? B[rb*Kk+ka] : 0.f;
    __syncthreads();
    #pragma unroll
    for (int kk=0;kk<16;kk++) acc += As[ty][kk]*Bs[tx][kk];
    __syncthreads();
  }
  if (row<M && col<Nn){
    if (bias) acc += bias[col];
    if (act==1) acc = 0.5f*acc*(1.f+erff(acc*0.70710678118654752f));
    Cmat[row*Nn+col]=acc;
  }
}

// ---------------- small-K softmax mixing: w[q,d] = q[q,d] * sum_k softmax(q·wk+wb)[k] * v[q,k,d] ----------------
__global__ void mix_kernel(const float* __restrict__ wk, const float* __restrict__ wb){
  int q=blockIdx.x, tid=threadIdx.x, warp=tid>>5, lane=tid&31;
  __shared__ float logits[8];
  __shared__ float kw[8];
  float p=0.f;
  for (int d=lane; d<DM; d+=32) p += g_q[q*DM+d]*wk[warp*DM+d];
  #pragma unroll
  for (int o=16;o;o>>=1) p += __shfl_down_sync(0xffffffffu,p,o);
  if (lane==0) logits[warp]=p+wb[warp];
  __syncthreads();
  if (tid==0){
    float m=logits[0];
    for (int k=1;k<8;k++) m=fmaxf(m,logits[k]);
    float s=0.f;
    for (int k=0;k<8;k++){ float e=expf(logits[k]-m); kw[k]=e; s+=e; }
    float inv=1.f/s;
    for (int k=0;k<8;k++) kw[k]*=inv;
  }
  __syncthreads();
  float acc=0.f;
  #pragma unroll
  for (int k=0;k<8;k++) acc += kw[k]*g_v[(q*8+k)*DM+tid];
  g_w[q*DM+tid] = g_q[q*DM+tid]*acc;
}

// ---------------- LayerNorm over 256: out = LN(a (+ b)) ----------------
__global__ void ln_kernel(float* __restrict__ out, const float* __restrict__ a,
                          const float* __restrict__ b){
  __shared__ float red[8];
  int row=blockIdx.x, tid=threadIdx.x;
  float v=a[row*DM+tid]; if (b) v+=b[row*DM+tid];
  float mean = blockSum256(v,red)*(1.f/DM);
  float d=v-mean;
  float var = blockSum256(d*d,red)*(1.f/DM);
  out[row*DM+tid]=d*rsqrtf(var+1e-5f);
}

__global__ void serialize_kernel(const int* __restrict__ order){
  int r=blockIdx.x;
  g_xs[r*DM+threadIdx.x] = g_xn[order[r]*DM+threadIdx.x];
}

// ---------------- causal depthwise conv (KC=4) + silu on proj[:, 512:1152] ----------------
__global__ void conv_silu_kernel(const float* __restrict__ wconv, const float* __restrict__ bconv){
  int id=blockIdx.x*blockDim.x+threadIdx.x;
  if (id>=2*QN*CONVN) return;
  int c=id%CONVN; int t=(id/CONVN)%QN; int b=id/(CONVN*QN);
  float acc=bconv[c];
  #pragma unroll
  for (int j=0;j<4;j++){
    int tt=t-3+j;
    if (tt>=0) acc += g_proj[(b*QN+tt)*NPROJN + DINN + c]*wconv[c*4+j];
  }
  g_xbc[id]=acc*sigmoidf_(acc);
}

// ---------------- dt = softplus(raw+dtb); chunk-local inclusive cumsum of dt*A ----------------
__global__ void dt_scan_kernel(const float* __restrict__ alog, const float* __restrict__ dtb){
  __shared__ float sc[CSZ];
  int bid=blockIdx.x;
  int c=bid%NCH, h=(bid/NCH)%NH, b=bid/(NCH*NH);
  int tid=threadIdx.x;
  int row=b*QN + c*CSZ + tid;
  float raw = g_proj[row*NPROJN + DINN+CONVN + h] + dtb[h];
  float dt = raw>20.f? raw : log1pf(expf(raw));
  g_dts[row*NH+h]=dt;
  float A=-expf(alog[h]);
  sc[tid]=dt*A;
  __syncthreads();
  for (int o=1;o<CSZ;o<<=1){
    float v=(tid>=o)? sc[tid-o]:0.f;
    __syncthreads();
    sc[tid]+=v;
    __syncthreads();
  }
  g_Las[row*NH+h]=sc[tid];
}

// ---------------- P[t,s] = [s<=t] * exp(La[t]-La[s]) * dt[s] * (C_t · B_s) ----------------
__global__ void chunkP_kernel(){
  __shared__ float Bt[CSZ][STATE+1], Ct[CSZ][STATE+1];
  __shared__ float La[CSZ], dtv[CSZ];
  int bid=blockIdx.x;
  int c=bid%NCH, h=(bid/NCH)%NH, b=bid/(NCH*NH);
  int tid=threadIdx.x;
  int r0=b*QN + c*CSZ;
  if (tid<CSZ){ La[tid]=g_Las[(r0+tid)*NH+h]; dtv[tid]=g_dts[(r0+tid)*NH+h]; }
  for (int i=tid;i<CSZ*STATE;i+=256){
    int s=i>>6, st=i&63;
    const float* xr=&g_xbc[(r0+s)*CONVN];
    Bt[s][st]=xr[DINN+st];
    Ct[s][st]=xr[DINN+STATE+st];
  }
  __syncthreads();
  int tb=(tid>>4)<<2, sb=(tid&15)<<2;
  float acc[4][4];
  #pragma unroll
  for (int i=0;i<4;i++){ acc[i][0]=0;acc[i][1]=0;acc[i][2]=0;acc[i][3]=0; }
  for (int k=0;k<STATE;k++){
    float cv[4], bv[4];
    #pragma unroll
    for (int i=0;i<4;i++) cv[i]=Ct[tb+i][k];
    #pragma unroll
    for (int j=0;j<4;j++) bv[j]=Bt[sb+j][k];
    #pragma unroll
    for (int i=0;i<4;i++)
      #pragma unroll
      for (int j=0;j<4;j++) acc[i][j]+=cv[i]*bv[j];
  }
  float* Pg=&g_P[bid*CSZ*CSZ];
  #pragma unroll
  for (int i=0;i<4;i++){
    int t=tb+i;
    #pragma unroll
    for (int j=0;j<4;j++){
      int s=sb+j;
      float val=0.f;
      if (s<=t) val=expf(La[t]-La[s])*dtv[s]*acc[i][j];
      Pg[t*CSZ+s]=val;
    }
  }
}

// ---------------- Hc[hd,st] = sum_s exp(Lend-La[s]) dt[s] B[s,st] x[s,hd] ----------------
__global__ void chunkH_kernel(){
  __shared__ float Xs[CSZ][HDIM], Bw[CSZ][STATE+1];
  __shared__ float La[CSZ], wv[CSZ];
  int bid=blockIdx.x;
  int c=bid%NCH, h=(bid/NCH)%NH, b=bid/(NCH*NH);
  int tid=threadIdx.x;
  int r0=b*QN + c*CSZ;
  if (tid<CSZ) La[tid]=g_Las[(r0+tid)*NH+h];
  __syncthreads();
  if (tid<CSZ) wv[tid]=expf(La[CSZ-1]-La[tid])*g_dts[(r0+tid)*NH+h];
  __syncthreads();
  for (int i=tid;i<CSZ*STATE;i+=256){
    int s=i>>6, k=i&63;
    const float* xr=&g_xbc[(r0+s)*CONVN];
    Xs[s][k]=xr[h*HDIM+k];
    Bw[s][k]=xr[DINN+k]*wv[s];
  }
  __syncthreads();
  int hb=(tid>>4)<<2, sb=(tid&15)<<2;
  float acc[4][4];
  #pragma unroll
  for (int i=0;i<4;i++){ acc[i][0]=0;acc[i][1]=0;acc[i][2]=0;acc[i][3]=0; }
  for (int s=0;s<CSZ;s++){
    float xv[4], bv[4];
    #pragma unroll
    for (int i=0;i<4;i++) xv[i]=Xs[s][hb+i];
    #pragma unroll
    for (int j=0;j<4;j++) bv[j]=Bw[s][sb+j];
    #pragma unroll
    for (int i=0;i<4;i++)
      #pragma unroll
      for (int j=0;j<4;j++) acc[i][j]+=xv[i]*bv[j];
  }
  float* Hg=&g_Hc[bid*HDIM*STATE];
  #pragma unroll
  for (int i=0;i<4;i++)
    #pragma unroll
    for (int j=0;j<4;j++)
      Hg[(hb+i)*STATE + sb+j]=acc[i][j];
}

// ---------------- sequential carry across 32 chunks (16 blocks, trivial) ----------------
__global__ void carry_kernel(){
  int bh=blockIdx.x;         // b*8+h
  int b=bh>>3, h=bh&7;
  int tid=threadIdx.x;       // 512 threads, 8 states each
  float hreg[8];
  #pragma unroll
  for (int i=0;i<8;i++) hreg[i]=0.f;
  for (int c=0;c<NCH;c++){
    float Lend=g_Las[(b*QN + c*CSZ + CSZ-1)*NH + h];
    float f=expf(Lend);
    int base=(bh*NCH+c)*HDIM*STATE;
    #pragma unroll
    for (int i=0;i<8;i++){
      int sidx=tid+i*512;
      g_Hin[base+sidx]=hreg[i];
      hreg[i]=f*hreg[i]+g_Hc[base+sidx];
    }
  }
}

// ---------------- y_intra: Y = P @ X + D[h]*X ----------------
__global__ void y_intra_kernel(const float* __restrict__ Dh){
  __shared__ float Ps[CSZ][CSZ+1], Xs[CSZ][HDIM];
  int bid=blockIdx.x;
  int c=bid%NCH, h=(bid/NCH)%NH, b=bid/(NCH*NH);
  int tid=threadIdx.x;
  int r0=b*QN + c*CSZ;
  const float* Pg=&g_P[bid*CSZ*CSZ];
  for (int i=tid;i<CSZ*CSZ;i+=256) Ps[i>>6][i&63]=Pg[i];
  for (int i=tid;i<CSZ*HDIM;i+=256){
    int s=i>>6,k=i&63;
    Xs[s][k]=g_xbc[(r0+s)*CONVN + h*HDIM + k];
  }
  __syncthreads();
  int tb=(tid>>4)<<2, hb=(tid&15)<<2;
  float acc[4][4];
  #pragma unroll
  for (int i=0;i<4;i++){ acc[i][0]=0;acc[i][1]=0;acc[i][2]=0;acc[i][3]=0; }
  for (int s=0;s<CSZ;s++){
    float pv[4], xv[4];
    #pragma unroll
    for (int i=0;i<4;i++) pv[i]=Ps[tb+i][s];
    #pragma unroll
    for (int j=0;j<4;j++) xv[j]=Xs[s][hb+j];
    #pragma unroll
    for (int i=0;i<4;i++)
      #pragma unroll
      for (int j=0;j<4;j++) acc[i][j]+=pv[i]*xv[j];
  }
  float dh=Dh[h];
  #pragma unroll
  for (int i=0;i<4;i++){
    int t=tb+i;
    #pragma unroll
    for (int j=0;j<4;j++){
      int hd=hb+j;
      g_y[(r0+t)*DINN + h*HDIM + hd] = acc[i][j] + dh*Xs[t][hd];
    }
  }
}

// ---------------- y_inter: Y += exp(La[t]) * (C_t · Hin[hd,:]) ----------------
__global__ void y_inter_kernel(){
  __shared__ float Ct[CSZ][STATE+1], Hi[HDIM][STATE+1], La[CSZ];
  int bid=blockIdx.x;
  int c=bid%NCH, h=(bid/NCH)%NH, b=bid/(NCH*NH);
  int tid=threadIdx.x;
  int r0=b*QN + c*CSZ;
  if (tid<CSZ) La[tid]=g_Las[(r0+tid)*NH+h];
  for (int i=tid;i<CSZ*STATE;i+=256){
    int t=i>>6,k=i&63;
    Ct[t][k]=g_xbc[(r0+t)*CONVN + DINN+STATE + k];
  }
  const float* Hg=&g_Hin[bid*HDIM*STATE];
  for (int i=tid;i<HDIM*STATE;i+=256) Hi[i>>6][i&63]=Hg[i];
  __syncthreads();
  int tb=(tid>>4)<<2, hb=(tid&15)<<2;
  float acc[4][4];
  #pragma unroll
  for (int i=0;i<4;i++){ acc[i][0]=0;acc[i][1]=0;acc[i][2]=0;acc[i][3]=0; }
  for (int k=0;k<STATE;k++){
    float cv[4], hv[4];
    #pragma unroll
    for (int i=0;i<4;i++) cv[i]=Ct[tb+i][k];
    #pragma unroll
    for (int j=0;j<4;j++) hv[j]=Hi[hb+j][k];
    #pragma unroll
    for (int i=0;i<4;i++)
      #pragma unroll
      for (int j=0;j<4;j++) acc[i][j]+=cv[i]*hv[j];
  }
  #pragma unroll
  for (int i=0;i<4;i++){
    int t=tb+i;
    float f=expf(La[t]);
    #pragma unroll
    for (int j=0;j<4;j++)
      g_y[(r0+t)*DINN + h*HDIM + hb+j] += f*acc[i][j];
  }
}

// ---------------- gated RMSNorm over DIN=512 ----------------
__global__ void gate_rms_kernel(const float* __restrict__ rmsw){
  __shared__ float red[8];
  int row=blockIdx.x, tid=threadIdx.x;
  float z0=g_proj[row*NPROJN+tid],     z1=g_proj[row*NPROJN+256+tid];
  float y0=g_y[row*DINN+tid],          y1=g_y[row*DINN+256+tid];
  float gg0=y0*(z0*sigmoidf_(z0));
  float gg1=y1*(z1*sigmoidf_(z1));
  float ssum=blockSum256(gg0*gg0+gg1*gg1,red);
  float r=rsqrtf(ssum*(1.f/DINN)+1e-5f);
  g_gated[row*DINN+tid]     = gg0*r*rmsw[tid];
  g_gated[row*DINN+256+tid] = gg1*r*rmsw[256+tid];
}

// ---------------- unsort + average + residual + LN (in-place on g_x) ----------------
__global__ void merge_ln_kernel(){
  __shared__ float red[8];
  int q=blockIdx.x, tid=threadIdx.x;
  float sc=g_x[q*DM+tid];
  int i0=g_inv[q], i1=g_inv[QN+q];
  float v=sc+0.5f*(g_ssmout[i0*DM+tid]+g_ssmout[(QN+i1)*DM+tid]);
  float mean=blockSum256(v,red)*(1.f/DM);
  float d=v-mean;
  float var=blockSum256(d*d,red)*(1.f/DM);
  g_x[q*DM+tid]=d*rsqrtf(var+1e-5f);
}

// =====================================================================
extern "C" void kernel_launch(void* const* d_in, const int* in_sizes, int n_in,
                              void* d_out, int out_size){
  const float* query      = (const float*)d_in[0];
  const float* query_pos  = (const float*)d_in[1];
  const float* inst_feats = (const float*)d_in[2];
  const float* sp_coords  = (const float*)d_in[3];
  const float* w_q  = (const float*)d_in[4];
  const float* w_v  = (const float*)d_in[5];
  const float* w_o  = (const float*)d_in[6];
  const float* w_k  = (const float*)d_in[7];
  const float* w_b  = (const float*)d_in[8];
  const float* Win  = (const float*)d_in[9];
  const float* Wconv= (const float*)d_in[10];
  const float* bconv= (const float*)d_in[11];
  const float* Alog = (const float*)d_in[12];
  const float* Dh   = (const float*)d_in[13];
  const float* dtb  = (const float*)d_in[14];
  const float* rmsw = (const float*)d_in[15];
  const float* Wout = (const float*)d_in[16];
  const float* fw1  = (const float*)d_in[17];
  const float* fb1  = (const float*)d_in[18];
  const float* fw2  = (const float*)d_in[19];
  const float* fb2  = (const float*)d_in[20];
  const int*   order= (const int*)  d_in[21];
  float* out = (float*)d_out;

  float *pq,*pfeat,*pv,*pw,*ptmp,*px,*pxn,*pxs,*pproj,*pgated,*pssm,*pffnh;
  cudaGetSymbolAddress((void**)&pq,    g_q);
  cudaGetSymbolAddress((void**)&pfeat, g_feat);
  cudaGetSymbolAddress((void**)&pv,    g_v);
  cudaGetSymbolAddress((void**)&pw,    g_w);
  cudaGetSymbolAddress((void**)&ptmp,  g_tmp);
  cudaGetSymbolAddress((void**)&px,    g_x);
  cudaGetSymbolAddress((void**)&pxn,   g_xn);
  cudaGetSymbolAddress((void**)&pxs,   g_xs);
  cudaGetSymbolAddress((void**)&pproj, g_proj);
  cudaGetSymbolAddress((void**)&pgated,g_gated);
  cudaGetSymbolAddress((void**)&pssm,  g_ssmout);
  cudaGetSymbolAddress((void**)&pffnh, g_ffnh);

  dim3 b16(16,16);
  auto grid=[](int m,int n){ return dim3((unsigned)((n+15)/16),(unsigned)((m+15)/16)); };

  // --- stage 1: KNN + mixing ---
  knn_kernel<<<QN/8,256>>>(query_pos, sp_coords);
  inv_kernel<<<(2*QN+255)/256,256>>>(order);
  gather_feat_kernel<<<QN*KNN,256>>>(inst_feats);
  gemm_kernel<<<grid(QN,DM),b16>>>(query, w_q, nullptr, pq, QN, DM, DM, 0);
  gemm_kernel<<<grid(QN*KNN,DM),b16>>>(pfeat, w_v, nullptr, pv, QN*KNN, DM, DM, 0);
  mix_kernel<<<QN,256>>>(w_k, w_b);
  gemm_kernel<<<grid(QN,DM),b16>>>(pw, w_o, nullptr, ptmp, QN, DM, DM, 0);
  ln_kernel<<<QN,256>>>(px, ptmp, query);

  // --- stage 2: two Mamba2 layers (chunked SSD form) ---
  for (int l=0;l<2;l++){
    ln_kernel<<<QN,256>>>(pxn, px, nullptr);
    serialize_kernel<<<2*QN,256>>>(order);
    gemm_kernel<<<grid(2*QN,NPROJN),b16>>>(pxs, Win + (size_t)l*NPROJN*DM, nullptr,
                                           pproj, 2*QN, NPROJN, DM, 0);
    conv_silu_kernel<<<(2*QN*CONVN+255)/256,256>>>(Wconv + (size_t)l*CONVN*4,
                                                   bconv + (size_t)l*CONVN);
    dt_scan_kernel<<<2*NH*NCH,CSZ>>>(Alog + l*NH, dtb + l*NH);
    chunkP_kernel<<<2*NH*NCH,256>>>();
    chunkH_kernel<<<2*NH*NCH,256>>>();
    carry_kernel<<<2*NH,512>>>();
    y_intra_kernel<<<2*NH*NCH,256>>>(Dh + l*NH);
    y_inter_kernel<<<2*NH*NCH,256>>>();
    gate_rms_kernel<<<2*QN,256>>>(rmsw + (size_t)l*DINN);
    gemm_kernel<<<grid(2*QN,DM),b16>>>(pgated, Wout + (size_t)l*DM*DINN, nullptr,
                                       pssm, 2*QN, DM, DINN, 0);
    merge_ln_kernel<<<QN,256>>>();
  }

  // --- stage 3: FFN + final LN ---
  gemm_kernel<<<grid(QN,HIDN),b16>>>(px, fw1, fb1, pffnh, QN, HIDN, DM, 1);
  gemm_kernel<<<grid(QN,DM),b16>>>(pffnh, fw2, fb2, ptmp, QN, DM, HIDN, 0);
  ln_kernel<<<QN,256>>>(out, ptmp, px);
}

// round 2
// speedup vs baseline: 2.2803x; 2.2803x over previous
#include <cuda_runtime.h>
#include <math.h>

#define QN 2048
#define NPTS 32768
#define DM 256
#define KNN 8
#define NH 8
#define HDIM 64
#define STATE 64
#define DINN 512
#define CONVN 640
#define NPROJN 1160
#define HIDN 1024
#define CSZ 64
#define NCH 32

// ---------------- scratch (device globals; no allocation allowed) ----------------
__device__ float g_q[QN*DM];
__device__ float g_fbar[QN*DM];
__device__ float g_vbar[QN*DM];
__device__ float g_w[QN*DM];
__device__ float g_x[QN*DM];
__device__ float g_xn[QN*DM];
__device__ float g_tmp[QN*DM];
__device__ int   g_idx[QN*KNN];
__device__ int   g_inv[2*QN];
__device__ float g_xs[2*QN*DM];
__device__ float g_proj[2*QN*NPROJN];
__device__ float g_xbc[2*QN*CONVN];
__device__ float g_dts[2*QN*NH];
__device__ float g_Las[2*QN*NH];
__device__ float g_P[2*NH*NCH*CSZ*CSZ];
__device__ float g_Hc[2*NH*NCH*HDIM*STATE];
__device__ float g_Hin[2*NH*NCH*HDIM*STATE];
__device__ float g_y[2*QN*DINN];
__device__ float g_gated[2*QN*DINN];
__device__ float g_ssmout[2*QN*DM];
__device__ float g_ffnh[QN*HIDN];

__device__ __forceinline__ float sigmoidf_(float x){ return 1.f/(1.f+expf(-x)); }

__device__ __forceinline__ float blockSum256(float v, volatile float* red){
  #pragma unroll
  for (int o=16;o;o>>=1) v += __shfl_down_sync(0xffffffffu, v, o);
  if ((threadIdx.x&31)==0) red[threadIdx.x>>5]=v;
  __syncthreads();
  float s = red[0]+red[1]+red[2]+red[3]+red[4]+red[5]+red[6]+red[7];
  __syncthreads();
  return s;
}

// ---------------- KNN: 1 warp per query, 8 queries/block, smem point tiles ----------------
#define TPTS 2048
__global__ void knn_kernel(const float* __restrict__ qpos, const float* __restrict__ spos){
  __shared__ float sp[TPTS*3];
  int warp = threadIdx.x>>5, lane = threadIdx.x&31;
  int q = blockIdx.x*8 + warp;
  float qx=qpos[q*3+0], qy=qpos[q*3+1], qz=qpos[q*3+2];
  float qq = qx*qx+qy*qy+qz*qz;
  float bd[8]; int bi[8];
  #pragma unroll
  for (int j=0;j<8;j++){ bd[j]=3.0e38f; bi[j]=0x7fffffff; }
  for (int tile=0;tile<NPTS/TPTS;tile++){
    __syncthreads();
    for (int i=threadIdx.x;i<TPTS*3;i+=256) sp[i]=spos[tile*TPTS*3+i];
    __syncthreads();
    for (int p=lane;p<TPTS;p+=32){
      float sx=sp[3*p], sy=sp[3*p+1], sz=sp[3*p+2];
      float ss = sx*sx+sy*sy+sz*sz;
      float dot = qx*sx+qy*sy+qz*sz;
      float d2 = qq + ss - 2.f*dot;
      if (d2 < bd[7]){
        bd[7]=d2; bi[7]=tile*TPTS+p;
        for (int j=7;j>0;j--){
          if (bd[j]<bd[j-1]){ float td=bd[j];bd[j]=bd[j-1];bd[j-1]=td;
                              int ti=bi[j];bi[j]=bi[j-1];bi[j-1]=ti; }
          else break;
        }
      }
    }
  }
  for (int off=16;off;off>>=1){
    float od[8]; int oi[8];
    #pragma unroll
    for (int j=0;j<8;j++){
      od[j]=__shfl_xor_sync(0xffffffffu,bd[j],off);
      oi[j]=__shfl_xor_sync(0xffffffffu,bi[j],off);
    }
    float nd[8]; int ni[8]; int a=0,c=0;
    for (int t=0;t<8;t++){
      bool mine;
      if (a>=8) mine=false;
      else if (c>=8) mine=true;
      else mine = (bd[a]<od[c]) || (bd[a]==od[c] && bi[a]<=oi[c]);
      if (mine){ nd[t]=bd[a];ni[t]=bi[a];a++; } else { nd[t]=od[c];ni[t]=oi[c];c++; }
    }
    for (int j=0;j<8;j++){ bd[j]=nd[j]; bi[j]=ni[j]; }
  }
  if (lane==0){
    #pragma unroll
    for (int j=0;j<8;j++) g_idx[q*8+j]=bi[j];
  }
}

__global__ void inv_kernel(const int* __restrict__ order){
  int id=blockIdx.x*blockDim.x+threadIdx.x;
  if (id<2*QN) g_inv[(id/QN)*QN + order[id]] = id%QN;
}

// ---------------- register-blocked SGEMM: C[M,N] = A[M,K] * B[N,K]^T ----------------
// 64x64 tile, BK=16, 256 threads, 4x4 micro-tile. Requires M%64==0, K%16==0.
#define BM 64
#define BN 64
#define BK 16
__global__ void sgemm_kernel(const float* __restrict__ A, const float* __restrict__ B,
                             const float* __restrict__ bias, float* __restrict__ Cmat,
                             int M, int Nn, int Kk, int act){
  __shared__ float As[BK][BM+4];
  __shared__ float Bs[BK][BN+4];
  int tid=threadIdx.x;
  int tx=tid&15, ty=tid>>4;
  int row0=blockIdx.y*BM, col0=blockIdx.x*BN;
  int lr=tid>>2, lc=(tid&3)<<2;
  const float* Arow = A + (size_t)(row0+lr)*Kk + lc;
  bool bvalid = (col0+lr)<Nn;
  const float* Brow = B + (size_t)(col0+lr)*Kk + lc;
  float acc[4][4];
  #pragma unroll
  for (int i=0;i<4;i++){ acc[i][0]=0;acc[i][1]=0;acc[i][2]=0;acc[i][3]=0; }
  for (int k0=0;k0<Kk;k0+=BK){
    float4 av = *(const float4*)(Arow + k0);
    float4 bv = bvalid ? *(const float4*)(Brow + k0) : make_float4(0.f,0.f,0.f,0.f);
    __syncthreads();
    As[lc+0][lr]=av.x; As[lc+1][lr]=av.y; As[lc+2][lr]=av.z; As[lc+3][lr]=av.w;
    Bs[lc+0][lr]=bv.x; Bs[lc+1][lr]=bv.y; Bs[lc+2][lr]=bv.z; Bs[lc+3][lr]=bv.w;
    __syncthreads();
    #pragma unroll
    for (int kk=0;kk<BK;kk++){
      float4 a=*(const float4*)&As[kk][ty<<2];
      float4 b=*(const float4*)&Bs[kk][tx<<2];
      acc[0][0]+=a.x*b.x; acc[0][1]+=a.x*b.y; acc[0][2]+=a.x*b.z; acc[0][3]+=a.x*b.w;
      acc[1][0]+=a.y*b.x; acc[1][1]+=a.y*b.y; acc[1][2]+=a.y*b.z; acc[1][3]+=a.y*b.w;
      acc[2][0]+=a.z*b.x; acc[2][1]+=a.z*b.y; acc[2][2]+=a.z*b.z; acc[2][3]+=a.z*b.w;
      acc[3][0]+=a.w*b.x; acc[3][1]+=a.w*b.y; acc[3][2]+=a.w*b.z; acc[3][3]+=a.w*b.w;
    }
  }
  #pragma unroll
  for (int i=0;i<4;i++){
    int row=row0+(ty<<2)+i;
    #pragma unroll
    for (int j=0;j<4;j++){
      int col=col0+(tx<<2)+j;
      if (col<Nn){
        float v=acc[i][j];
        if (bias) v+=bias[col];
        if (act==1) v = 0.5f*v*(1.f+erff(v*0.70710678118654752f));
        Cmat[(size_t)row*Nn+col]=v;
      }
    }
  }
}

// ---------------- mixing weights + weighted feature blend (linearity trick) ----------------
// fbar[q,:] = sum_k softmax(q.wk+wb)[k] * inst_feats[idx[q,k],:]
__global__ void mixbar_kernel(const float* __restrict__ wk, const float* __restrict__ wb,
                              const float* __restrict__ feats){
  int q=blockIdx.x, tid=threadIdx.x, warp=tid>>5, lane=tid&31;
  __shared__ float logits[8];
  __shared__ float kw[8];
  __shared__ int   sidx[8];
  float p=0.f;
  for (int d=lane; d<DM; d+=32) p += g_q[q*DM+d]*wk[warp*DM+d];
  #pragma unroll
  for (int o=16;o;o>>=1) p += __shfl_down_sync(0xffffffffu,p,o);
  if (lane==0) logits[warp]=p+wb[warp];
  if (tid<8) sidx[tid]=g_idx[q*8+tid];
  __syncthreads();
  if (tid==0){
    float m=logits[0];
    for (int k=1;k<8;k++) m=fmaxf(m,logits[k]);
    float s=0.f;
    for (int k=0;k<8;k++){ float e=expf(logits[k]-m); kw[k]=e; s+=e; }
    float inv=1.f/s;
    for (int k=0;k<8;k++) kw[k]*=inv;
  }
  __syncthreads();
  float acc=0.f;
  #pragma unroll
  for (int k=0;k<8;k++) acc += kw[k]*feats[(size_t)sidx[k]*DM+tid];
  g_fbar[q*DM+tid]=acc;
}

__global__ void wmul_kernel(){
  int i=blockIdx.x*blockDim.x+threadIdx.x;
  g_w[i]=g_q[i]*g_vbar[i];
}

// ---------------- LayerNorm over 256: out = LN(a (+ b)) ----------------
__global__ void ln_kernel(float* __restrict__ out, const float* __restrict__ a,
                          const float* __restrict__ b){
  __shared__ float red[8];
  int row=blockIdx.x, tid=threadIdx.x;
  float v=a[row*DM+tid]; if (b) v+=b[row*DM+tid];
  float mean = blockSum256(v,red)*(1.f/DM);
  float d=v-mean;
  float var = blockSum256(d*d,red)*(1.f/DM);
  out[row*DM+tid]=d*rsqrtf(var+1e-5f);
}

__global__ void serialize_kernel(const int* __restrict__ order){
  int r=blockIdx.x;
  g_xs[r*DM+threadIdx.x] = g_xn[order[r]*DM+threadIdx.x];
}

// ---------------- causal depthwise conv (KC=4) + silu ----------------
__global__ void conv_silu_kernel(const float* __restrict__ wconv, const float* __restrict__ bconv){
  int id=blockIdx.x*blockDim.x+threadIdx.x;
  if (id>=2*QN*CONVN) return;
  int c=id%CONVN; int t=(id/CONVN)%QN; int b=id/(CONVN*QN);
  float acc=bconv[c];
  #pragma unroll
  for (int j=0;j<4;j++){
    int tt=t-3+j;
    if (tt>=0) acc += g_proj[(size_t)(b*QN+tt)*NPROJN + DINN + c]*wconv[c*4+j];
  }
  g_xbc[id]=acc*sigmoidf_(acc);
}

// ---------------- dt = softplus(raw+dtb); chunk-local inclusive cumsum of dt*A ----------------
__global__ void dt_scan_kernel(const float* __restrict__ alog, const float* __restrict__ dtb){
  __shared__ float sc[CSZ];
  int bid=blockIdx.x;
  int c=bid%NCH, h=(bid/NCH)%NH, b=bid/(NCH*NH);
  int tid=threadIdx.x;
  int row=b*QN + c*CSZ + tid;
  float raw = g_proj[(size_t)row*NPROJN + DINN+CONVN + h] + dtb[h];
  float dt = raw>20.f? raw : log1pf(expf(raw));
  g_dts[row*NH+h]=dt;
  float A=-expf(alog[h]);
  sc[tid]=dt*A;
  __syncthreads();
  for (int o=1;o<CSZ;o<<=1){
    float v=(tid>=o)? sc[tid-o]:0.f;
    __syncthreads();
    sc[tid]+=v;
    __syncthreads();
  }
  g_Las[row*NH+h]=sc[tid];
}

// ---------------- P[t,s] = [s<=t] * exp(La[t]-La[s]) * dt[s] * (C_t . B_s) ----------------
__global__ void chunkP_kernel(){
  __shared__ float Bt[CSZ][STATE+1], Ct[CSZ][STATE+1];
  __shared__ float La[CSZ], dtv[CSZ];
  int bid=blockIdx.x;
  int c=bid%NCH, h=(bid/NCH)%NH, b=bid/(NCH*NH);
  int tid=threadIdx.x;
  int r0=b*QN + c*CSZ;
  if (tid<CSZ){ La[tid]=g_Las[(r0+tid)*NH+h]; dtv[tid]=g_dts[(r0+tid)*NH+h]; }
  for (int i=tid;i<CSZ*STATE;i+=256){
    int s=i>>6, st=i&63;
    const float* xr=&g_xbc[(size_t)(r0+s)*CONVN];
    Bt[s][st]=xr[DINN+st];
    Ct[s][st]=xr[DINN+STATE+st];
  }
  __syncthreads();
  int tb=(tid>>4)<<2, sb=(tid&15)<<2;
  float acc[4][4];
  #pragma unroll
  for (int i=0;i<4;i++){ acc[i][0]=0;acc[i][1]=0;acc[i][2]=0;acc[i][3]=0; }
  for (int k=0;k<STATE;k++){
    float cv[4], bv[4];
    #pragma unroll
    for (int i=0;i<4;i++) cv[i]=Ct[tb+i][k];
    #pragma unroll
    for (int j=0;j<4;j++) bv[j]=Bt[sb+j][k];
    #pragma unroll
    for (int i=0;i<4;i++)
      #pragma unroll
      for (int j=0;j<4;j++) acc[i][j]+=cv[i]*bv[j];
  }
  float* Pg=&g_P[(size_t)bid*CSZ*CSZ];
  #pragma unroll
  for (int i=0;i<4;i++){
    int t=tb+i;
    #pragma unroll
    for (int j=0;j<4;j++){
      int s=sb+j;
      float val=0.f;
      if (s<=t) val=expf(La[t]-La[s])*dtv[s]*acc[i][j];
      Pg[t*CSZ+s]=val;
    }
  }
}

// ---------------- Hc[hd,st] = sum_s exp(Lend-La[s]) dt[s] B[s,st] x[s,hd] ----------------
__global__ void chunkH_kernel(){
  __shared__ float Xs[CSZ][HDIM], Bw[CSZ][STATE+1];
  __shared__ float La[CSZ], wv[CSZ];
  int bid=blockIdx.x;
  int c=bid%NCH, h=(bid/NCH)%NH, b=bid/(NCH*NH);
  int tid=threadIdx.x;
  int r0=b*QN + c*CSZ;
  if (tid<CSZ) La[tid]=g_Las[(r0+tid)*NH+h];
  __syncthreads();
  if (tid<CSZ) wv[tid]=expf(La[CSZ-1]-La[tid])*g_dts[(r0+tid)*NH+h];
  __syncthreads();
  for (int i=tid;i<CSZ*STATE;i+=256){
    int s=i>>6, k=i&63;
    const float* xr=&g_xbc[(size_t)(r0+s)*CONVN];
    Xs[s][k]=xr[h*HDIM+k];
    Bw[s][k]=xr[DINN+k]*wv[s];
  }
  __syncthreads();
  int hb=(tid>>4)<<2, sb=(tid&15)<<2;
  float acc[4][4];
  #pragma unroll
  for (int i=0;i<4;i++){ acc[i][0]=0;acc[i][1]=0;acc[i][2]=0;acc[i][3]=0; }
  for (int s=0;s<CSZ;s++){
    float xv[4], bv[4];
    #pragma unroll
    for (int i=0;i<4;i++) xv[i]=Xs[s][hb+i];
    #pragma unroll
    for (int j=0;j<4;j++) bv[j]=Bw[s][sb+j];
    #pragma unroll
    for (int i=0;i<4;i++)
      #pragma unroll
      for (int j=0;j<4;j++) acc[i][j]+=xv[i]*bv[j];
  }
  float* Hg=&g_Hc[(size_t)bid*HDIM*STATE];
  #pragma unroll
  for (int i=0;i<4;i++)
    #pragma unroll
    for (int j=0;j<4;j++)
      Hg[(hb+i)*STATE + sb+j]=acc[i][j];
}

// ---------------- sequential carry across 32 chunks ----------------
__global__ void carry_kernel(){
  int bh=blockIdx.x;
  int b=bh>>3, h=bh&7;
  int tid=threadIdx.x;
  float hreg[8];
  #pragma unroll
  for (int i=0;i<8;i++) hreg[i]=0.f;
  for (int c=0;c<NCH;c++){
    float Lend=g_Las[(b*QN + c*CSZ + CSZ-1)*NH + h];
    float f=expf(Lend);
    size_t base=(size_t)(bh*NCH+c)*HDIM*STATE;
    #pragma unroll
    for (int i=0;i<8;i++){
      int sidx=tid+i*512;
      g_Hin[base+sidx]=hreg[i];
      hreg[i]=f*hreg[i]+g_Hc[base+sidx];
    }
  }
}

// ---------------- y_intra: Y = P @ X + D[h]*X ----------------
__global__ void y_intra_kernel(const float* __restrict__ Dh){
  __shared__ float Ps[CSZ][CSZ+1], Xs[CSZ][HDIM];
  int bid=blockIdx.x;
  int c=bid%NCH, h=(bid/NCH)%NH, b=bid/(NCH*NH);
  int tid=threadIdx.x;
  int r0=b*QN + c*CSZ;
  const float* Pg=&g_P[(size_t)bid*CSZ*CSZ];
  for (int i=tid;i<CSZ*CSZ;i+=256) Ps[i>>6][i&63]=Pg[i];
  for (int i=tid;i<CSZ*HDIM;i+=256){
    int s=i>>6,k=i&63;
    Xs[s][k]=g_xbc[(size_t)(r0+s)*CONVN + h*HDIM + k];
  }
  __syncthreads();
  int tb=(tid>>4)<<2, hb=(tid&15)<<2;
  float acc[4][4];
  #pragma unroll
  for (int i=0;i<4;i++){ acc[i][0]=0;acc[i][1]=0;acc[i][2]=0;acc[i][3]=0; }
  for (int s=0;s<CSZ;s++){
    float pv[4], xv[4];
    #pragma unroll
    for (int i=0;i<4;i++) pv[i]=Ps[tb+i][s];
    #pragma unroll
    for (int j=0;j<4;j++) xv[j]=Xs[s][hb+j];
    #pragma unroll
    for (int i=0;i<4;i++)
      #pragma unroll
      for (int j=0;j<4;j++) acc[i][j]+=pv[i]*xv[j];
  }
  float dh=Dh[h];
  #pragma unroll
  for (int i=0;i<4;i++){
    int t=tb+i;
    #pragma unroll
    for (int j=0;j<4;j++){
      int hd=hb+j;
      g_y[(size_t)(r0+t)*DINN + h*HDIM + hd] = acc[i][j] + dh*Xs[t][hd];
    }
  }
}

// ---------------- y_inter: Y += exp(La[t]) * (C_t . Hin[hd,:]) ----------------
__global__ void y_inter_kernel(){
  __shared__ float Ct[CSZ][STATE+1], Hi[HDIM][STATE+1], La[CSZ];
  int bid=blockIdx.x;
  int c=bid%NCH, h=(bid/NCH)%NH, b=bid/(NCH*NH);
  int tid=threadIdx.x;
  int r0=b*QN + c*CSZ;
  if (tid<CSZ) La[tid]=g_Las[(r0+tid)*NH+h];
  for (int i=tid;i<CSZ*STATE;i+=256){
    int t=i>>6,k=i&63;
    Ct[t][k]=g_xbc[(size_t)(r0+t)*CONVN + DINN+STATE + k];
  }
  const float* Hg=&g_Hin[(size_t)bid*HDIM*STATE];
  for (int i=tid;i<HDIM*STATE;i+=256) Hi[i>>6][i&63]=Hg[i];
  __syncthreads();
  int tb=(tid>>4)<<2, hb=(tid&15)<<2;
  float acc[4][4];
  #pragma unroll
  for (int i=0;i<4;i++){ acc[i][0]=0;acc[i][1]=0;acc[i][2]=0;acc[i][3]=0; }
  for (int k=0;k<STATE;k++){
    float cv[4], hv[4];
    #pragma unroll
    for (int i=0;i<4;i++) cv[i]=Ct[tb+i][k];
    #pragma unroll
    for (int j=0;j<4;j++) hv[j]=Hi[hb+j][k];
    #pragma unroll
    for (int i=0;i<4;i++)
      #pragma unroll
      for (int j=0;j<4;j++) acc[i][j]+=cv[i]*hv[j];
  }
  #pragma unroll
  for (int i=0;i<4;i++){
    int t=tb+i;
    float f=expf(La[t]);
    #pragma unroll
    for (int j=0;j<4;j++)
      g_y[(size_t)(r0+t)*DINN + h*HDIM + hb+j] += f*acc[i][j];
  }
}

// ---------------- gated RMSNorm over DIN=512 ----------------
__global__ void gate_rms_kernel(const float* __restrict__ rmsw){
  __shared__ float red[8];
  int row=blockIdx.x, tid=threadIdx.x;
  float z0=g_proj[(size_t)row*NPROJN+tid],     z1=g_proj[(size_t)row*NPROJN+256+tid];
  float y0=g_y[(size_t)row*DINN+tid],          y1=g_y[(size_t)row*DINN+256+tid];
  float gg0=y0*(z0*sigmoidf_(z0));
  float gg1=y1*(z1*sigmoidf_(z1));
  float ssum=blockSum256(gg0*gg0+gg1*gg1,red);
  float r=rsqrtf(ssum*(1.f/DINN)+1e-5f);
  g_gated[(size_t)row*DINN+tid]     = gg0*r*rmsw[tid];
  g_gated[(size_t)row*DINN+256+tid] = gg1*r*rmsw[256+tid];
}

// ---------------- unsort + average + residual + LN (in-place on g_x) ----------------
__global__ void merge_ln_kernel(){
  __shared__ float red[8];
  int q=blockIdx.x, tid=threadIdx.x;
  float sc=g_x[q*DM+tid];
  int i0=g_inv[q], i1=g_inv[QN+q];
  float v=sc+0.5f*(g_ssmout[i0*DM+tid]+g_ssmout[(QN+i1)*DM+tid]);
  float mean=blockSum256(v,red)*(1.f/DM);
  float d=v-mean;
  float var=blockSum256(d*d,red)*(1.f/DM);
  g_x[q*DM+tid]=d*rsqrtf(var+1e-5f);
}

// =====================================================================
extern "C" void kernel_launch(void* const* d_in, const int* in_sizes, int n_in,
                              void* d_out, int out_size){
  const float* query      = (const float*)d_in[0];
  const float* query_pos  = (const float*)d_in[1];
  const float* inst_feats = (const float*)d_in[2];
  const float* sp_coords  = (const float*)d_in[3];
  const float* w_q  = (const float*)d_in[4];
  const float* w_v  = (const float*)d_in[5];
  const float* w_o  = (const float*)d_in[6];
  const float* w_k  = (const float*)d_in[7];
  const float* w_b  = (const float*)d_in[8];
  const float* Win  = (const float*)d_in[9];
  const float* Wconv= (const float*)d_in[10];
  const float* bconv= (const float*)d_in[11];
  const float* Alog = (const float*)d_in[12];
  const float* Dh   = (const float*)d_in[13];
  const float* dtb  = (const float*)d_in[14];
  const float* rmsw = (const float*)d_in[15];
  const float* Wout = (const float*)d_in[16];
  const float* fw1  = (const float*)d_in[17];
  const float* fb1  = (const float*)d_in[18];
  const float* fw2  = (const float*)d_in[19];
  const float* fb2  = (const float*)d_in[20];
  const int*   order= (const int*)  d_in[21];
  float* out = (float*)d_out;

  float *pq,*pfbar,*pvbar,*pw,*ptmp,*px,*pxn,*pxs,*pproj,*pgated,*pssm,*pffnh;
  cudaGetSymbolAddress((void**)&pq,    g_q);
  cudaGetSymbolAddress((void**)&pfbar, g_fbar);
  cudaGetSymbolAddress((void**)&pvbar, g_vbar);
  cudaGetSymbolAddress((void**)&pw,    g_w);
  cudaGetSymbolAddress((void**)&ptmp,  g_tmp);
  cudaGetSymbolAddress((void**)&px,    g_x);
  cudaGetSymbolAddress((void**)&pxn,   g_xn);
  cudaGetSymbolAddress((void**)&pxs,   g_xs);
  cudaGetSymbolAddress((void**)&pproj, g_proj);
  cudaGetSymbolAddress((void**)&pgated,g_gated);
  cudaGetSymbolAddress((void**)&pssm,  g_ssmout);
  cudaGetSymbolAddress((void**)&pffnh, g_ffnh);

  auto grid=[](int m,int n){ return dim3((unsigned)((n+BN-1)/BN),(unsigned)(m/BM)); };

  // --- stage 1: KNN + mixing ---
  knn_kernel<<<QN/8,256>>>(query_pos, sp_coords);
  inv_kernel<<<(2*QN+255)/256,256>>>(order);
  sgemm_kernel<<<grid(QN,DM),256>>>(query, w_q, nullptr, pq, QN, DM, DM, 0);
  mixbar_kernel<<<QN,256>>>(w_k, w_b, inst_feats);
  sgemm_kernel<<<grid(QN,DM),256>>>(pfbar, w_v, nullptr, pvbar, QN, DM, DM, 0);
  wmul_kernel<<<QN*DM/256,256>>>();
  sgemm_kernel<<<grid(QN,DM),256>>>(pw, w_o, nullptr, ptmp, QN, DM, DM, 0);
  ln_kernel<<<QN,256>>>(px, ptmp, query);

  // --- stage 2: two Mamba2 layers (chunked SSD form) ---
  for (int l=0;l<2;l++){
    ln_kernel<<<QN,256>>>(pxn, px, nullptr);
    serialize_kernel<<<2*QN,256>>>(order);
    sgemm_kernel<<<grid(2*QN,NPROJN),256>>>(pxs, Win + (size_t)l*NPROJN*DM, nullptr,
                                            pproj, 2*QN, NPROJN, DM, 0);
    conv_silu_kernel<<<(2*QN*CONVN+255)/256,256>>>(Wconv + (size_t)l*CONVN*4,
                                                   bconv + (size_t)l*CONVN);
    dt_scan_kernel<<<2*NH*NCH,CSZ>>>(Alog + l*NH, dtb + l*NH);
    chunkP_kernel<<<2*NH*NCH,256>>>();
    chunkH_kernel<<<2*NH*NCH,256>>>();
    carry_kernel<<<2*NH,512>>>();
    y_intra_kernel<<<2*NH*NCH,256>>>(Dh + l*NH);
    y_inter_kernel<<<2*NH*NCH,256>>>();
    gate_rms_kernel<<<2*QN,256>>>(rmsw + (size_t)l*DINN);
    sgemm_kernel<<<grid(2*QN,DM),256>>>(pgated, Wout + (size_t)l*DM*DINN, nullptr,
                                        pssm, 2*QN, DM, DINN, 0);
    merge_ln_kernel<<<QN,256>>>();
  }

  // --- stage 3: FFN + final LN ---
  sgemm_kernel<<<grid(QN,HIDN),256>>>(px, fw1, fb1, pffnh, QN, HIDN, DM, 1);
  sgemm_kernel<<<grid(QN,DM),256>>>(pffnh, fw2, fb2, ptmp, QN, DM, HIDN, 0);
  ln_kernel<<<QN,256>>>(out, ptmp, px);
}

// round 3
// speedup vs baseline: 2.6872x; 1.1784x over previous
#include <cuda_runtime.h>
#include <math.h>
#include <stdint.h>

#define QN 2048
#define NPTS 32768
#define DM 256
#define KNN 8
#define NH 8
#define HDIM 64
#define STATE 64
#define DINN 512
#define CONVN 640
#define NPROJN 1160
#define HIDN 1024
#define CSZ 64
#define NCH 32

// ---------------- scratch (device globals; no allocation allowed) ----------------
__device__ float g_q[QN*DM];
__device__ float g_fbar[QN*DM];
__device__ float g_vbar[QN*DM];
__device__ float g_w[QN*DM];
__device__ float g_x[QN*DM];
__device__ float g_xn[QN*DM];
__device__ float g_tmp[QN*DM];
__device__ int   g_idx[QN*KNN];
__device__ int   g_inv[2*QN];
__device__ float g_xs[2*QN*DM];
__device__ float g_proj[2*QN*NPROJN];
__device__ float g_xbc[2*QN*CONVN];
__device__ float g_dts[2*QN*NH];
__device__ float g_Las[2*QN*NH];
__device__ float g_P[2*NH*NCH*CSZ*CSZ];
__device__ float g_Hc[2*NH*NCH*HDIM*STATE];
__device__ float g_Hin[2*NH*NCH*HDIM*STATE];
__device__ float g_y[2*QN*DINN];
__device__ float g_gated[2*QN*DINN];
__device__ float g_ssmout[2*QN*DM];
__device__ float g_ffnh[QN*HIDN];

__device__ __forceinline__ float sigmoidf_(float x){ return 1.f/(1.f+expf(-x)); }
__device__ __forceinline__ float to_tf32(float x){
  float r; asm("cvt.rna.tf32.f32 %0, %1;" : "=f"(r) : "f"(x)); return r;
}

__device__ __forceinline__ float blockSum256(float v, volatile float* red){
  #pragma unroll
  for (int o=16;o;o>>=1) v += __shfl_down_sync(0xffffffffu, v, o);
  if ((threadIdx.x&31)==0) red[threadIdx.x>>5]=v;
  __syncthreads();
  float s = red[0]+red[1]+red[2]+red[3]+red[4]+red[5]+red[6]+red[7];
  __syncthreads();
  return s;
}

// ---------------- KNN ----------------
#define TPTS 2048
__global__ void knn_kernel(const float* __restrict__ qpos, const float* __restrict__ spos){
  __shared__ float sp[TPTS*3];
  int warp = threadIdx.x>>5, lane = threadIdx.x&31;
  int q = blockIdx.x*8 + warp;
  float qx=qpos[q*3+0], qy=qpos[q*3+1], qz=qpos[q*3+2];
  float qq = qx*qx+qy*qy+qz*qz;
  float bd[8]; int bi[8];
  #pragma unroll
  for (int j=0;j<8;j++){ bd[j]=3.0e38f; bi[j]=0x7fffffff; }
  for (int tile=0;tile<NPTS/TPTS;tile++){
    __syncthreads();
    for (int i=threadIdx.x;i<TPTS*3;i+=256) sp[i]=spos[tile*TPTS*3+i];
    __syncthreads();
    for (int p=lane;p<TPTS;p+=32){
      float sx=sp[3*p], sy=sp[3*p+1], sz=sp[3*p+2];
      float ss = sx*sx+sy*sy+sz*sz;
      float dot = qx*sx+qy*sy+qz*sz;
      float d2 = qq + ss - 2.f*dot;
      if (d2 < bd[7]){
        bd[7]=d2; bi[7]=tile*TPTS+p;
        for (int j=7;j>0;j--){
          if (bd[j]<bd[j-1]){ float td=bd[j];bd[j]=bd[j-1];bd[j-1]=td;
                              int ti=bi[j];bi[j]=bi[j-1];bi[j-1]=ti; }
          else break;
        }
      }
    }
  }
  for (int off=16;off;off>>=1){
    float od[8]; int oi[8];
    #pragma unroll
    for (int j=0;j<8;j++){
      od[j]=__shfl_xor_sync(0xffffffffu,bd[j],off);
      oi[j]=__shfl_xor_sync(0xffffffffu,bi[j],off);
    }
    float nd[8]; int ni[8]; int a=0,c=0;
    for (int t=0;t<8;t++){
      bool mine;
      if (a>=8) mine=false;
      else if (c>=8) mine=true;
      else mine = (bd[a]<od[c]) || (bd[a]==od[c] && bi[a]<=oi[c]);
      if (mine){ nd[t]=bd[a];ni[t]=bi[a];a++; } else { nd[t]=od[c];ni[t]=oi[c];c++; }
    }
    for (int j=0;j<8;j++){ bd[j]=nd[j]; bi[j]=ni[j]; }
  }
  if (lane==0){
    #pragma unroll
    for (int j=0;j<8;j++) g_idx[q*8+j]=bi[j];
  }
}

__global__ void inv_kernel(const int* __restrict__ order){
  int id=blockIdx.x*blockDim.x+threadIdx.x;
  if (id<2*QN) g_inv[(id/QN)*QN + order[id]] = id%QN;
}

// ---------------- tf32 tensor-core GEMM: C[M,N] = A[M,K] * B[N,K]^T ----------------
// 128x64x16 tiles, 256 threads (8 warps, 4x2 warp grid, 32x32 warp tile),
// mma.sync.m16n8k8.tf32 with fp32 accumulate. Requires M%128==0, K%16==0.
#define TBM 128
#define TBN 64
#define TBK 16
__global__ void __launch_bounds__(256) tgemm_kernel(
    const float* __restrict__ A, const float* __restrict__ B,
    const float* __restrict__ bias, float* __restrict__ Cmat,
    int M, int Nn, int Kk, int act){
  __shared__ float As[TBM][TBK+4];
  __shared__ float Bs[TBN][TBK+4];
  int tid=threadIdx.x;
  int warp=tid>>5, lane=tid&31;
  int wm=(warp&3)*32, wn=(warp>>2)*32;
  int g=lane>>2, tig=lane&3;
  int row0=blockIdx.y*TBM, col0=blockIdx.x*TBN;

  float acc[2][4][4];
  #pragma unroll
  for (int mi=0;mi<2;mi++)
    #pragma unroll
    for (int ni=0;ni<4;ni++)
      #pragma unroll
      for (int r=0;r<4;r++) acc[mi][ni][r]=0.f;

  int aRow0=tid>>2, aC4=(tid&3)<<2;          // + second load at tid+256
  int aRow1=(tid+256)>>2;
  int bRow=tid>>2, bC4=(tid&3)<<2;
  bool bValid=(col0+bRow)<Nn;
  const float* Ap0=A+(size_t)(row0+aRow0)*Kk+aC4;
  const float* Ap1=A+(size_t)(row0+aRow1)*Kk+aC4;
  const float* Bp =B+(size_t)(col0+bRow)*Kk+bC4;

  for (int k0=0;k0<Kk;k0+=TBK){
    float4 av0=*(const float4*)(Ap0+k0);
    float4 av1=*(const float4*)(Ap1+k0);
    float4 bv = bValid? *(const float4*)(Bp+k0) : make_float4(0.f,0.f,0.f,0.f);
    __syncthreads();
    float4 t0=make_float4(to_tf32(av0.x),to_tf32(av0.y),to_tf32(av0.z),to_tf32(av0.w));
    float4 t1=make_float4(to_tf32(av1.x),to_tf32(av1.y),to_tf32(av1.z),to_tf32(av1.w));
    float4 tb=make_float4(to_tf32(bv.x),to_tf32(bv.y),to_tf32(bv.z),to_tf32(bv.w));
    *(float4*)&As[aRow0][aC4]=t0;
    *(float4*)&As[aRow1][aC4]=t1;
    *(float4*)&Bs[bRow][bC4]=tb;
    __syncthreads();
    #pragma unroll
    for (int ks=0;ks<TBK;ks+=8){
      uint32_t af[2][4], bf[4][2];
      #pragma unroll
      for (int mi=0;mi<2;mi++){
        int m=wm+mi*16+g;
        af[mi][0]=__float_as_uint(As[m  ][ks+tig  ]);
        af[mi][1]=__float_as_uint(As[m+8][ks+tig  ]);
        af[mi][2]=__float_as_uint(As[m  ][ks+tig+4]);
        af[mi][3]=__float_as_uint(As[m+8][ks+tig+4]);
      }
      #pragma unroll
      for (int ni=0;ni<4;ni++){
        int n=wn+ni*8+g;
        bf[ni][0]=__float_as_uint(Bs[n][ks+tig  ]);
        bf[ni][1]=__float_as_uint(Bs[n][ks+tig+4]);
      }
      #pragma unroll
      for (int mi=0;mi<2;mi++)
        #pragma unroll
        for (int ni=0;ni<4;ni++){
          asm volatile(
            "mma.sync.aligned.m16n8k8.row.col.f32.tf32.tf32.f32 "
            "{%0,%1,%2,%3}, {%4,%5,%6,%7}, {%8,%9}, {%0,%1,%2,%3};"
            : "+f"(acc[mi][ni][0]),"+f"(acc[mi][ni][1]),
              "+f"(acc[mi][ni][2]),"+f"(acc[mi][ni][3])
            : "r"(af[mi][0]),"r"(af[mi][1]),"r"(af[mi][2]),"r"(af[mi][3]),
              "r"(bf[ni][0]),"r"(bf[ni][1]));
        }
    }
  }
  #pragma unroll
  for (int mi=0;mi<2;mi++){
    int r=row0+wm+mi*16+g;
    #pragma unroll
    for (int ni=0;ni<4;ni++){
      int c=col0+wn+ni*8+2*tig;
      #pragma unroll
      for (int half=0;half<2;half++){
        int rr=r+half*8;
        #pragma unroll
        for (int cc=0;cc<2;cc++){
          int col=c+cc;
          if (col<Nn){
            float v=acc[mi][ni][half*2+cc];
            if (bias) v+=bias[col];
            if (act==1) v=0.5f*v*(1.f+erff(v*0.70710678118654752f));
            Cmat[(size_t)rr*Nn+col]=v;
          }
        }
      }
    }
  }
}

// ---------------- mixing weights + weighted feature blend ----------------
__global__ void mixbar_kernel(const float* __restrict__ wk, const float* __restrict__ wb,
                              const float* __restrict__ feats){
  int q=blockIdx.x, tid=threadIdx.x, warp=tid>>5, lane=tid&31;
  __shared__ float logits[8];
  __shared__ float kw[8];
  __shared__ int   sidx[8];
  float p=0.f;
  for (int d=lane; d<DM; d+=32) p += g_q[q*DM+d]*wk[warp*DM+d];
  #pragma unroll
  for (int o=16;o;o>>=1) p += __shfl_down_sync(0xffffffffu,p,o);
  if (lane==0) logits[warp]=p+wb[warp];
  if (tid<8) sidx[tid]=g_idx[q*8+tid];
  __syncthreads();
  if (tid==0){
    float m=logits[0];
    for (int k=1;k<8;k++) m=fmaxf(m,logits[k]);
    float s=0.f;
    for (int k=0;k<8;k++){ float e=expf(logits[k]-m); kw[k]=e; s+=e; }
    float inv=1.f/s;
    for (int k=0;k<8;k++) kw[k]*=inv;
  }
  __syncthreads();
  float acc=0.f;
  #pragma unroll
  for (int k=0;k<8;k++) acc += kw[k]*feats[(size_t)sidx[k]*DM+tid];
  g_fbar[q*DM+tid]=acc;
}

__global__ void wmul_kernel(){
  int i=blockIdx.x*blockDim.x+threadIdx.x;
  g_w[i]=g_q[i]*g_vbar[i];
}

// ---------------- LayerNorm over 256 ----------------
__global__ void ln_kernel(float* __restrict__ out, const float* __restrict__ a,
                          const float* __restrict__ b){
  __shared__ float red[8];
  int row=blockIdx.x, tid=threadIdx.x;
  float v=a[row*DM+tid]; if (b) v+=b[row*DM+tid];
  float mean = blockSum256(v,red)*(1.f/DM);
  float d=v-mean;
  float var = blockSum256(d*d,red)*(1.f/DM);
  out[row*DM+tid]=d*rsqrtf(var+1e-5f);
}

__global__ void serialize_kernel(const int* __restrict__ order){
  int r=blockIdx.x;
  g_xs[r*DM+threadIdx.x] = g_xn[order[r]*DM+threadIdx.x];
}

// ---------------- causal depthwise conv + silu ----------------
__global__ void conv_silu_kernel(const float* __restrict__ wconv, const float* __restrict__ bconv){
  int id=blockIdx.x*blockDim.x+threadIdx.x;
  if (id>=2*QN*CONVN) return;
  int c=id%CONVN; int t=(id/CONVN)%QN; int b=id/(CONVN*QN);
  float acc=bconv[c];
  #pragma unroll
  for (int j=0;j<4;j++){
    int tt=t-3+j;
    if (tt>=0) acc += g_proj[(size_t)(b*QN+tt)*NPROJN + DINN + c]*wconv[c*4+j];
  }
  g_xbc[id]=acc*sigmoidf_(acc);
}

// ---------------- dt softplus + chunk-local cumsum ----------------
__global__ void dt_scan_kernel(const float* __restrict__ alog, const float* __restrict__ dtb){
  __shared__ float sc[CSZ];
  int bid=blockIdx.x;
  int c=bid%NCH, h=(bid/NCH)%NH, b=bid/(NCH*NH);
  int tid=threadIdx.x;
  int row=b*QN + c*CSZ + tid;
  float raw = g_proj[(size_t)row*NPROJN + DINN+CONVN + h] + dtb[h];
  float dt = raw>20.f? raw : log1pf(expf(raw));
  g_dts[row*NH+h]=dt;
  float A=-expf(alog[h]);
  sc[tid]=dt*A;
  __syncthreads();
  for (int o=1;o<CSZ;o<<=1){
    float v=(tid>=o)? sc[tid-o]:0.f;
    __syncthreads();
    sc[tid]+=v;
    __syncthreads();
  }
  g_Las[row*NH+h]=sc[tid];
}

// ---------------- P[t,s] ----------------
__global__ void chunkP_kernel(){
  __shared__ float Bt[CSZ][STATE+1], Ct[CSZ][STATE+1];
  __shared__ float La[CSZ], dtv[CSZ];
  int bid=blockIdx.x;
  int c=bid%NCH, h=(bid/NCH)%NH, b=bid/(NCH*NH);
  int tid=threadIdx.x;
  int r0=b*QN + c*CSZ;
  if (tid<CSZ){ La[tid]=g_Las[(r0+tid)*NH+h]; dtv[tid]=g_dts[(r0+tid)*NH+h]; }
  for (int i=tid;i<CSZ*STATE;i+=256){
    int s=i>>6, st=i&63;
    const float* xr=&g_xbc[(size_t)(r0+s)*CONVN];
    Bt[s][st]=xr[DINN+st];
    Ct[s][st]=xr[DINN+STATE+st];
  }
  __syncthreads();
  int tb=(tid>>4)<<2, sb=(tid&15)<<2;
  float acc[4][4];
  #pragma unroll
  for (int i=0;i<4;i++){ acc[i][0]=0;acc[i][1]=0;acc[i][2]=0;acc[i][3]=0; }
  for (int k=0;k<STATE;k++){
    float cv[4], bv[4];
    #pragma unroll
    for (int i=0;i<4;i++) cv[i]=Ct[tb+i][k];
    #pragma unroll
    for (int j=0;j<4;j++) bv[j]=Bt[sb+j][k];
    #pragma unroll
    for (int i=0;i<4;i++)
      #pragma unroll
      for (int j=0;j<4;j++) acc[i][j]+=cv[i]*bv[j];
  }
  float* Pg=&g_P[(size_t)bid*CSZ*CSZ];
  #pragma unroll
  for (int i=0;i<4;i++){
    int t=tb+i;
    #pragma unroll
    for (int j=0;j<4;j++){
      int s=sb+j;
      float val=0.f;
      if (s<=t) val=expf(La[t]-La[s])*dtv[s]*acc[i][j];
      Pg[t*CSZ+s]=val;
    }
  }
}

// ---------------- chunk states ----------------
__global__ void chunkH_kernel(){
  __shared__ float Xs[CSZ][HDIM], Bw[CSZ][STATE+1];
  __shared__ float La[CSZ], wv[CSZ];
  int bid=blockIdx.x;
  int c=bid%NCH, h=(bid/NCH)%NH, b=bid/(NCH*NH);
  int tid=threadIdx.x;
  int r0=b*QN + c*CSZ;
  if (tid<CSZ) La[tid]=g_Las[(r0+tid)*NH+h];
  __syncthreads();
  if (tid<CSZ) wv[tid]=expf(La[CSZ-1]-La[tid])*g_dts[(r0+tid)*NH+h];
  __syncthreads();
  for (int i=tid;i<CSZ*STATE;i+=256){
    int s=i>>6, k=i&63;
    const float* xr=&g_xbc[(size_t)(r0+s)*CONVN];
    Xs[s][k]=xr[h*HDIM+k];
    Bw[s][k]=xr[DINN+k]*wv[s];
  }
  __syncthreads();
  int hb=(tid>>4)<<2, sb=(tid&15)<<2;
  float acc[4][4];
  #pragma unroll
  for (int i=0;i<4;i++){ acc[i][0]=0;acc[i][1]=0;acc[i][2]=0;acc[i][3]=0; }
  for (int s=0;s<CSZ;s++){
    float xv[4], bv[4];
    #pragma unroll
    for (int i=0;i<4;i++) xv[i]=Xs[s][hb+i];
    #pragma unroll
    for (int j=0;j<4;j++) bv[j]=Bw[s][sb+j];
    #pragma unroll
    for (int i=0;i<4;i++)
      #pragma unroll
      for (int j=0;j<4;j++) acc[i][j]+=xv[i]*bv[j];
  }
  float* Hg=&g_Hc[(size_t)bid*HDIM*STATE];
  #pragma unroll
  for (int i=0;i<4;i++)
    #pragma unroll
    for (int j=0;j<4;j++)
      Hg[(hb+i)*STATE + sb+j]=acc[i][j];
}

// ---------------- carry ----------------
__global__ void carry_kernel(){
  int bh=blockIdx.x;
  int b=bh>>3, h=bh&7;
  int tid=threadIdx.x;
  float hreg[8];
  #pragma unroll
  for (int i=0;i<8;i++) hreg[i]=0.f;
  for (int c=0;c<NCH;c++){
    float Lend=g_Las[(b*QN + c*CSZ + CSZ-1)*NH + h];
    float f=expf(Lend);
    size_t base=(size_t)(bh*NCH+c)*HDIM*STATE;
    #pragma unroll
    for (int i=0;i<8;i++){
      int sidx=tid+i*512;
      g_Hin[base+sidx]=hreg[i];
      hreg[i]=f*hreg[i]+g_Hc[base+sidx];
    }
  }
}

// ---------------- y_intra ----------------
__global__ void y_intra_kernel(const float* __restrict__ Dh){
  __shared__ float Ps[CSZ][CSZ+1], Xs[CSZ][HDIM];
  int bid=blockIdx.x;
  int c=bid%NCH, h=(bid/NCH)%NH, b=bid/(NCH*NH);
  int tid=threadIdx.x;
  int r0=b*QN + c*CSZ;
  const float* Pg=&g_P[(size_t)bid*CSZ*CSZ];
  for (int i=tid;i<CSZ*CSZ;i+=256) Ps[i>>6][i&63]=Pg[i];
  for (int i=tid;i<CSZ*HDIM;i+=256){
    int s=i>>6,k=i&63;
    Xs[s][k]=g_xbc[(size_t)(r0+s)*CONVN + h*HDIM + k];
  }
  __syncthreads();
  int tb=(tid>>4)<<2, hb=(tid&15)<<2;
  float acc[4][4];
  #pragma unroll
  for (int i=0;i<4;i++){ acc[i][0]=0;acc[i][1]=0;acc[i][2]=0;acc[i][3]=0; }
  for (int s=0;s<CSZ;s++){
    float pv[4], xv[4];
    #pragma unroll
    for (int i=0;i<4;i++) pv[i]=Ps[tb+i][s];
    #pragma unroll
    for (int j=0;j<4;j++) xv[j]=Xs[s][hb+j];
    #pragma unroll
    for (int i=0;i<4;i++)
      #pragma unroll
      for (int j=0;j<4;j++) acc[i][j]+=pv[i]*xv[j];
  }
  float dh=Dh[h];
  #pragma unroll
  for (int i=0;i<4;i++){
    int t=tb+i;
    #pragma unroll
    for (int j=0;j<4;j++){
      int hd=hb+j;
      g_y[(size_t)(r0+t)*DINN + h*HDIM + hd] = acc[i][j] + dh*Xs[t][hd];
    }
  }
}

// ---------------- y_inter ----------------
__global__ void y_inter_kernel(){
  __shared__ float Ct[CSZ][STATE+1], Hi[HDIM][STATE+1], La[CSZ];
  int bid=blockIdx.x;
  int c=bid%NCH, h=(bid/NCH)%NH, b=bid/(NCH*NH);
  int tid=threadIdx.x;
  int r0=b*QN + c*CSZ;
  if (tid<CSZ) La[tid]=g_Las[(r0+tid)*NH+h];
  for (int i=tid;i<CSZ*STATE;i+=256){
    int t=i>>6,k=i&63;
    Ct[t][k]=g_xbc[(size_t)(r0+t)*CONVN + DINN+STATE + k];
  }
  const float* Hg=&g_Hin[(size_t)bid*HDIM*STATE];
  for (int i=tid;i<HDIM*STATE;i+=256) Hi[i>>6][i&63]=Hg[i];
  __syncthreads();
  int tb=(tid>>4)<<2, hb=(tid&15)<<2;
  float acc[4][4];
  #pragma unroll
  for (int i=0;i<4;i++){ acc[i][0]=0;acc[i][1]=0;acc[i][2]=0;acc[i][3]=0; }
  for (int k=0;k<STATE;k++){
    float cv[4], hv[4];
    #pragma unroll
    for (int i=0;i<4;i++) cv[i]=Ct[tb+i][k];
    #pragma unroll
    for (int j=0;j<4;j++) hv[j]=Hi[hb+j][k];
    #pragma unroll
    for (int i=0;i<4;i++)
      #pragma unroll
      for (int j=0;j<4;j++) acc[i][j]+=cv[i]*hv[j];
  }
  #pragma unroll
  for (int i=0;i<4;i++){
    int t=tb+i;
    float f=expf(La[t]);
    #pragma unroll
    for (int j=0;j<4;j++)
      g_y[(size_t)(r0+t)*DINN + h*HDIM + hb+j] += f*acc[i][j];
  }
}

// ---------------- gated RMSNorm ----------------
__global__ void gate_rms_kernel(const float* __restrict__ rmsw){
  __shared__ float red[8];
  int row=blockIdx.x, tid=threadIdx.x;
  float z0=g_proj[(size_t)row*NPROJN+tid],     z1=g_proj[(size_t)row*NPROJN+256+tid];
  float y0=g_y[(size_t)row*DINN+tid],          y1=g_y[(size_t)row*DINN+256+tid];
  float gg0=y0*(z0*sigmoidf_(z0));
  float gg1=y1*(z1*sigmoidf_(z1));
  float ssum=blockSum256(gg0*gg0+gg1*gg1,red);
  float r=rsqrtf(ssum*(1.f/DINN)+1e-5f);
  g_gated[(size_t)row*DINN+tid]     = gg0*r*rmsw[tid];
  g_gated[(size_t)row*DINN+256+tid] = gg1*r*rmsw[256+tid];
}

// ---------------- unsort + average + residual + LN ----------------
__global__ void merge_ln_kernel(){
  __shared__ float red[8];
  int q=blockIdx.x, tid=threadIdx.x;
  float sc=g_x[q*DM+tid];
  int i0=g_inv[q], i1=g_inv[QN+q];
  float v=sc+0.5f*(g_ssmout[i0*DM+tid]+g_ssmout[(QN+i1)*DM+tid]);
  float mean=blockSum256(v,red)*(1.f/DM);
  float d=v-mean;
  float var=blockSum256(d*d,red)*(1.f/DM);
  g_x[q*DM+tid]=d*rsqrtf(var+1e-5f);
}

// =====================================================================
extern "C" void kernel_launch(void* const* d_in, const int* in_sizes, int n_in,
                              void* d_out, int out_size){
  const float* query      = (const float*)d_in[0];
  const float* query_pos  = (const float*)d_in[1];
  const float* inst_feats = (const float*)d_in[2];
  const float* sp_coords  = (const float*)d_in[3];
  const float* w_q  = (const float*)d_in[4];
  const float* w_v  = (const float*)d_in[5];
  const float* w_o  = (const float*)d_in[6];
  const float* w_k  = (const float*)d_in[7];
  const float* w_b  = (const float*)d_in[8];
  const float* Win  = (const float*)d_in[9];
  const float* Wconv= (const float*)d_in[10];
  const float* bconv= (const float*)d_in[11];
  const float* Alog = (const float*)d_in[12];
  const float* Dh   = (const float*)d_in[13];
  const float* dtb  = (const float*)d_in[14];
  const float* rmsw = (const float*)d_in[15];
  const float* Wout = (const float*)d_in[16];
  const float* fw1  = (const float*)d_in[17];
  const float* fb1  = (const float*)d_in[18];
  const float* fw2  = (const float*)d_in[19];
  const float* fb2  = (const float*)d_in[20];
  const int*   order= (const int*)  d_in[21];
  float* out = (float*)d_out;

  float *pq,*pfbar,*pvbar,*pw,*ptmp,*px,*pxn,*pxs,*pproj,*pgated,*pssm,*pffnh;
  cudaGetSymbolAddress((void**)&pq,    g_q);
  cudaGetSymbolAddress((void**)&pfbar, g_fbar);
  cudaGetSymbolAddress((void**)&pvbar, g_vbar);
  cudaGetSymbolAddress((void**)&pw,    g_w);
  cudaGetSymbolAddress((void**)&ptmp,  g_tmp);
  cudaGetSymbolAddress((void**)&px,    g_x);
  cudaGetSymbolAddress((void**)&pxn,   g_xn);
  cudaGetSymbolAddress((void**)&pxs,   g_xs);
  cudaGetSymbolAddress((void**)&pproj, g_proj);
  cudaGetSymbolAddress((void**)&pgated,g_gated);
  cudaGetSymbolAddress((void**)&pssm,  g_ssmout);
  cudaGetSymbolAddress((void**)&pffnh, g_ffnh);

  auto tgrid=[](int m,int n){ return dim3((unsigned)((n+TBN-1)/TBN),(unsigned)(m/TBM)); };

  // --- stage 1: KNN + mixing ---
  knn_kernel<<<QN/8,256>>>(query_pos, sp_coords);
  inv_kernel<<<(2*QN+255)/256,256>>>(order);
  tgemm_kernel<<<tgrid(QN,DM),256>>>(query, w_q, nullptr, pq, QN, DM, DM, 0);
  mixbar_kernel<<<QN,256>>>(w_k, w_b, inst_feats);
  tgemm_kernel<<<tgrid(QN,DM),256>>>(pfbar, w_v, nullptr, pvbar, QN, DM, DM, 0);
  wmul_kernel<<<QN*DM/256,256>>>();
  tgemm_kernel<<<tgrid(QN,DM),256>>>(pw, w_o, nullptr, ptmp, QN, DM, DM, 0);
  ln_kernel<<<QN,256>>>(px, ptmp, query);

  // --- stage 2: two Mamba2 layers (chunked SSD form) ---
  for (int l=0;l<2;l++){
    ln_kernel<<<QN,256>>>(pxn, px, nullptr);
    serialize_kernel<<<2*QN,256>>>(order);
    tgemm_kernel<<<tgrid(2*QN,NPROJN),256>>>(pxs, Win + (size_t)l*NPROJN*DM, nullptr,
                                             pproj, 2*QN, NPROJN, DM, 0);
    conv_silu_kernel<<<(2*QN*CONVN+255)/256,256>>>(Wconv + (size_t)l*CONVN*4,
                                                   bconv + (size_t)l*CONVN);
    dt_scan_kernel<<<2*NH*NCH,CSZ>>>(Alog + l*NH, dtb + l*NH);
    chunkP_kernel<<<2*NH*NCH,256>>>();
    chunkH_kernel<<<2*NH*NCH,256>>>();
    carry_kernel<<<2*NH,512>>>();
    y_intra_kernel<<<2*NH*NCH,256>>>(Dh + l*NH);
    y_inter_kernel<<<2*NH*NCH,256>>>();
    gate_rms_kernel<<<2*QN,256>>>(rmsw + (size_t)l*DINN);
    tgemm_kernel<<<tgrid(2*QN,DM),256>>>(pgated, Wout + (size_t)l*DM*DINN, nullptr,
                                         pssm, 2*QN, DM, DINN, 0);
    merge_ln_kernel<<<QN,256>>>();
  }

  // --- stage 3: FFN + final LN ---
  tgemm_kernel<<<tgrid(QN,HIDN),256>>>(px, fw1, fb1, pffnh, QN, HIDN, DM, 1);
  tgemm_kernel<<<tgrid(QN,DM),256>>>(pffnh, fw2, fb2, ptmp, QN, DM, HIDN, 0);
  ln_kernel<<<QN,256>>>(out, ptmp, px);
}